// round 2
// baseline (speedup 1.0000x reference)
#include <cuda_runtime.h>
#include <math.h>

#define T_SEQ   4096
#define C_DIM   768
#define H_NUM   12
#define D_HEAD  64
#define QKV_N   (3 * C_DIM)

typedef unsigned long long ull;

// Scratch (allocation-free)
__device__ float g_qkv[T_SEQ * QKV_N];
__device__ float g_y[T_SEQ * C_DIM];

// ---------------- packed f32x2 helpers (Blackwell FFMA2) ----------------
__device__ __forceinline__ ull pack2(float lo, float hi) {
    ull r; asm("mov.b64 %0, {%1, %2};" : "=l"(r) : "f"(lo), "f"(hi)); return r;
}
__device__ __forceinline__ void unpack2(ull v, float& lo, float& hi) {
    asm("mov.b64 {%0, %1}, %2;" : "=f"(lo), "=f"(hi) : "l"(v));
}
__device__ __forceinline__ ull fma2(ull a, ull b, ull c) {
    ull d; asm("fma.rn.f32x2 %0, %1, %2, %3;" : "=l"(d) : "l"(a), "l"(b), "l"(c)); return d;
}
__device__ __forceinline__ ull mul2(ull a, ull b) {
    ull d; asm("mul.rn.f32x2 %0, %1, %2;" : "=l"(d) : "l"(a), "l"(b)); return d;
}

// ----------------------------------------------------------------------------
// Tiled SGEMM with fused bias, packed f32x2 microtile.
// C[M,N] = A[M,K] @ B[K,N] + bias[N]. BM=BN=128, BK=16, 256 threads, 8x8 tile.
// ----------------------------------------------------------------------------
__global__ __launch_bounds__(256) void sgemm_bias_kernel(
    const float* __restrict__ A, const float* __restrict__ B,
    const float* __restrict__ bias, float* __restrict__ Cm,
    int M, int N, int K)
{
    constexpr int BM = 128, BN = 128, BK = 16, TM = 8;
    __shared__ alignas(16) float As[BK][BM];
    __shared__ alignas(16) float Bs[BK][BN];

    const int tid  = threadIdx.x;
    const int brow = blockIdx.y * BM;
    const int bcol = blockIdx.x * BN;
    const int trow = (tid / 16) * TM;
    const int tcol = (tid % 16) * TM;

    ull acc2[TM][4];
#pragma unroll
    for (int i = 0; i < TM; i++)
#pragma unroll
        for (int j = 0; j < 4; j++) acc2[i][j] = 0ull;

    for (int k0 = 0; k0 < K; k0 += BK) {
#pragma unroll
        for (int i = 0; i < 2; i++) {
            int m = (tid >> 2) + i * 64;
            int k = (tid & 3) * 4;
            float4 v = *(const float4*)&A[(size_t)(brow + m) * K + k0 + k];
            As[k + 0][m] = v.x;
            As[k + 1][m] = v.y;
            As[k + 2][m] = v.z;
            As[k + 3][m] = v.w;
        }
#pragma unroll
        for (int i = 0; i < 2; i++) {
            int k = (tid >> 5) + i * 8;
            int n = (tid & 31) * 4;
            *(float4*)&Bs[k][n] = *(const float4*)&B[(size_t)(k0 + k) * N + bcol + n];
        }
        __syncthreads();

#pragma unroll
        for (int kk = 0; kk < BK; kk++) {
            float4 ra0 = *(const float4*)&As[kk][trow];
            float4 ra1 = *(const float4*)&As[kk][trow + 4];
            ulonglong2 rbA = ((const ulonglong2*)&Bs[kk][tcol])[0];
            ulonglong2 rbB = ((const ulonglong2*)&Bs[kk][tcol])[1];
            ull rb2[4] = { rbA.x, rbA.y, rbB.x, rbB.y };
            float ra[TM] = { ra0.x, ra0.y, ra0.z, ra0.w, ra1.x, ra1.y, ra1.z, ra1.w };
#pragma unroll
            for (int i = 0; i < TM; i++) {
                ull ra2 = pack2(ra[i], ra[i]);
#pragma unroll
                for (int j = 0; j < 4; j++)
                    acc2[i][j] = fma2(ra2, rb2[j], acc2[i][j]);
            }
        }
        __syncthreads();
    }

#pragma unroll
    for (int i = 0; i < TM; i++) {
        float c[8];
#pragma unroll
        for (int j = 0; j < 4; j++) unpack2(acc2[i][j], c[2 * j], c[2 * j + 1]);
#pragma unroll
        for (int j = 0; j < 8; j += 4) {
            float4 v;
            v.x = c[j + 0] + bias[bcol + tcol + j + 0];
            v.y = c[j + 1] + bias[bcol + tcol + j + 1];
            v.z = c[j + 2] + bias[bcol + tcol + j + 2];
            v.w = c[j + 3] + bias[bcol + tcol + j + 3];
            *(float4*)&Cm[(size_t)(brow + trow + i) * N + bcol + tcol + j] = v;
        }
    }
}

// ----------------------------------------------------------------------------
// Causal flash attention, fp32 with packed f32x2 math.
// One query per thread, 128 queries per block, grid = (T/128, H).
// 32-key SMEM tiles; scores computed 8 keys at a time, single rescale per 8.
// Causal handled by masking scores to -1e30 (no divergent loop bounds).
// ----------------------------------------------------------------------------
__global__ __launch_bounds__(128) void flash_attn_kernel()
{
    const int h  = blockIdx.y;
    const int qi = blockIdx.x * 128 + threadIdx.x;
    const float scale = 0.125f;  // 1/sqrt(64)

    ull q2[32];
    {
        const float* qptr = &g_qkv[(size_t)qi * QKV_N + h * D_HEAD];
#pragma unroll
        for (int d = 0; d < D_HEAD; d += 4) {
            float4 v = *(const float4*)&qptr[d];
            q2[d / 2]     = pack2(v.x * scale, v.y * scale);
            q2[d / 2 + 1] = pack2(v.z * scale, v.w * scale);
        }
    }

    ull acc2[32];
#pragma unroll
    for (int i = 0; i < 32; i++) acc2[i] = 0ull;
    float m = -1e30f;
    float l = 0.0f;

    __shared__ alignas(16) float Ks[32][D_HEAD];
    __shared__ alignas(16) float Vs[32][D_HEAD];

    const int kend = blockIdx.x * 128 + 128;
    for (int kt = 0; kt < kend; kt += 32) {
        // Cooperative tile load (coalesced float4)
#pragma unroll
        for (int i = 0; i < 4; i++) {
            int lin = threadIdx.x + i * 128;
            int r = lin >> 4;
            int c = (lin & 15) * 4;
            const float* base = &g_qkv[(size_t)(kt + r) * QKV_N + h * D_HEAD + c];
            *(float4*)&Ks[r][c] = *(const float4*)&base[C_DIM];
            *(float4*)&Vs[r][c] = *(const float4*)&base[2 * C_DIM];
        }
        __syncthreads();

#pragma unroll
        for (int sub = 0; sub < 32; sub += 8) {
            float s[8];
#pragma unroll
            for (int j = 0; j < 8; j++) {
                const ulonglong2* kr = (const ulonglong2*)Ks[sub + j];
                ull p0 = 0ull, p1 = 0ull, p2 = 0ull, p3 = 0ull;
#pragma unroll
                for (int i = 0; i < 16; i += 2) {
                    ulonglong2 a = kr[i];
                    ulonglong2 b = kr[i + 1];
                    p0 = fma2(q2[2 * i + 0], a.x, p0);
                    p1 = fma2(q2[2 * i + 1], a.y, p1);
                    p2 = fma2(q2[2 * i + 2], b.x, p2);
                    p3 = fma2(q2[2 * i + 3], b.y, p3);
                }
                float a0, a1, b0, b1, c0, c1, d0, d1;
                unpack2(p0, a0, a1); unpack2(p1, b0, b1);
                unpack2(p2, c0, c1); unpack2(p3, d0, d1);
                float sv = ((a0 + a1) + (b0 + b1)) + ((c0 + c1) + (d0 + d1));
                s[j] = (kt + sub + j <= qi) ? sv : -1e30f;
            }

            float mt = s[0];
#pragma unroll
            for (int j = 1; j < 8; j++) mt = fmaxf(mt, s[j]);
            float mn = fmaxf(m, mt);
            float corr = __expf(m - mn);
            m = mn;
            l *= corr;
            ull corr2 = pack2(corr, corr);
#pragma unroll
            for (int i = 0; i < 32; i++) acc2[i] = mul2(acc2[i], corr2);

#pragma unroll
            for (int j = 0; j < 8; j++) {
                float pw = __expf(s[j] - mn);
                l += pw;
                ull pw2 = pack2(pw, pw);
                const ulonglong2* vr = (const ulonglong2*)Vs[sub + j];
#pragma unroll
                for (int i = 0; i < 16; i++) {
                    ulonglong2 vv = vr[i];
                    acc2[2 * i + 0] = fma2(pw2, vv.x, acc2[2 * i + 0]);
                    acc2[2 * i + 1] = fma2(pw2, vv.y, acc2[2 * i + 1]);
                }
            }
        }
        __syncthreads();
    }

    const float inv = 1.0f / l;
    float* yptr = &g_y[(size_t)qi * C_DIM + h * D_HEAD];
#pragma unroll
    for (int i = 0; i < 32; i += 2) {
        float x0, x1, x2, x3;
        unpack2(acc2[i], x0, x1);
        unpack2(acc2[i + 1], x2, x3);
        float4 v = { x0 * inv, x1 * inv, x2 * inv, x3 * inv };
        *(float4*)&yptr[2 * i] = v;
    }
}

// ----------------------------------------------------------------------------
extern "C" void kernel_launch(void* const* d_in, const int* in_sizes, int n_in,
                              void* d_out, int out_size)
{
    const float* x      = (const float*)d_in[0];
    const float* w_attn = (const float*)d_in[1];
    const float* b_attn = (const float*)d_in[2];
    const float* w_proj = (const float*)d_in[3];
    const float* b_proj = (const float*)d_in[4];
    float* out = (float*)d_out;

    float* qkv = nullptr;
    float* y   = nullptr;
    cudaGetSymbolAddress((void**)&qkv, g_qkv);
    cudaGetSymbolAddress((void**)&y, g_y);

    sgemm_bias_kernel<<<dim3(QKV_N / 128, T_SEQ / 128), 256>>>(
        x, w_attn, b_attn, qkv, T_SEQ, QKV_N, C_DIM);

    flash_attn_kernel<<<dim3(T_SEQ / 128, H_NUM), 128>>>();

    sgemm_bias_kernel<<<dim3(C_DIM / 128, T_SEQ / 128), 256>>>(
        y, w_proj, b_proj, out, T_SEQ, C_DIM, C_DIM);
}

// round 3
// speedup vs baseline: 6.5034x; 6.5034x over previous
#include <cuda_runtime.h>
#include <cuda_fp16.h>
#include <stdint.h>

#define T_SEQ   4096
#define C_DIM   768
#define H_NUM   12
#define D_HEAD  64
#define QKV_N   2304

// ------------------------- scratch (allocation-free) -------------------------
__device__ __half g_xh  [T_SEQ * C_DIM];
__device__ __half g_wah [C_DIM * QKV_N];
__device__ __half g_wph [C_DIM * C_DIM];
__device__ __half g_qkvh[T_SEQ * QKV_N];
__device__ __half g_vt  [C_DIM * T_SEQ];   // V transposed: [channel(h*64+d)][t]
__device__ __half g_yh  [T_SEQ * C_DIM];

// ------------------------------ helpers --------------------------------------
__device__ __forceinline__ void mma16816(float* c,
    uint32_t a0, uint32_t a1, uint32_t a2, uint32_t a3,
    uint32_t b0, uint32_t b1)
{
    asm volatile(
        "mma.sync.aligned.m16n8k16.row.col.f32.f16.f16.f32 "
        "{%0,%1,%2,%3},{%4,%5,%6,%7},{%8,%9},{%0,%1,%2,%3};"
        : "+f"(c[0]), "+f"(c[1]), "+f"(c[2]), "+f"(c[3])
        : "r"(a0), "r"(a1), "r"(a2), "r"(a3), "r"(b0), "r"(b1));
}

__device__ __forceinline__ uint32_t packf2h(float lo, float hi) {
    uint32_t r;
    asm("cvt.rn.f16x2.f32 %0, %1, %2;" : "=r"(r) : "f"(hi), "f"(lo));
    return r;
}

// ------------------------- fp32 -> fp16 conversion ---------------------------
__global__ void cvt_f2h(const float4* __restrict__ src, uint2* __restrict__ dst, int n4)
{
    int i = blockIdx.x * blockDim.x + threadIdx.x;
    if (i >= n4) return;
    float4 v = src[i];
    uint2 o;
    o.x = packf2h(v.x, v.y);
    o.y = packf2h(v.z, v.w);
    dst[i] = o;
}

// ------------------- V transpose: [t][1536 + c] -> [c][t] ---------------------
__global__ __launch_bounds__(256) void transpose_v()
{
    __shared__ __half tile[32][36];
    const int tb = blockIdx.x * 32;        // token base
    const int cb = blockIdx.y * 32;        // channel base (0..767)
    const int r  = threadIdx.x >> 3;       // 0..31
    const int c4 = (threadIdx.x & 7) * 4;  // 0..28

    *(uint2*)&tile[r][c4] =
        *(const uint2*)&g_qkvh[(size_t)(tb + r) * QKV_N + 1536 + cb + c4];
    __syncthreads();

    __half2 h0 = __halves2half2(tile[c4 + 0][r], tile[c4 + 1][r]);
    __half2 h1 = __halves2half2(tile[c4 + 2][r], tile[c4 + 3][r]);
    uint2 o = { *(uint32_t*)&h0, *(uint32_t*)&h1 };
    *(uint2*)&g_vt[(size_t)(cb + r) * T_SEQ + tb + c4] = o;
}

// ----------------------- fp16 MMA GEMM with fused bias -----------------------
// C[M,N] = A[M,K](fp16) @ B[K,N](fp16) + bias(f32).  Block 128x128x32,
// 256 threads = 8 warps (4 along M x 2 along N), warp tile 32x64.
template<bool OUT_F32>
__global__ __launch_bounds__(256) void hgemm_bias(
    const __half* __restrict__ A, const __half* __restrict__ B,
    const float* __restrict__ bias, void* __restrict__ Cout,
    int M, int N, int K)
{
    __shared__ __half   As[128][40];      // [m][k] padded
    __shared__ uint32_t Bs[128][18];      // [n][k-pair] padded (each u32 = fp16 k,k+1)

    const int tid = threadIdx.x;
    const int l   = tid & 31;
    const int wid = tid >> 5;
    const int wm  = (wid & 3) * 32;       // warp m offset
    const int wn  = (wid >> 2) * 64;      // warp n offset
    const int brow = blockIdx.y * 128;
    const int bcol = blockIdx.x * 128;

    // A tile loader: thread -> (row, 32B half-row)
    const int ar = tid >> 1, ah = tid & 1;
    // B tile loader: thread -> (k-pair, 8-wide n group)
    const int kp = tid & 15, ng = tid >> 4;

    float acc[2][8][4];
#pragma unroll
    for (int mi = 0; mi < 2; mi++)
#pragma unroll
        for (int nt = 0; nt < 8; nt++)
#pragma unroll
            for (int j = 0; j < 4; j++) acc[mi][nt][j] = 0.0f;

    const int NK = K / 32;
    uint4 apf0, apf1, bpf0, bpf1;

    // prologue load (k-tile 0)
    {
        const uint4* ap = (const uint4*)(A + (size_t)(brow + ar) * K + ah * 16);
        apf0 = ap[0]; apf1 = ap[1];
        const __half* b0p = B + (size_t)(2 * kp) * N + bcol + ng * 8;
        bpf0 = *(const uint4*)b0p;
        bpf1 = *(const uint4*)(b0p + N);
    }

    for (int kt = 0; kt < NK; kt++) {
        // store staged tile to SMEM
        *(uint4*)&As[ar][ah * 16 + 0] = apf0;
        *(uint4*)&As[ar][ah * 16 + 8] = apf1;
        {
            const uint32_t* u = (const uint32_t*)&bpf0;
            const uint32_t* w = (const uint32_t*)&bpf1;
#pragma unroll
            for (int j = 0; j < 4; j++) {
                Bs[ng * 8 + 2 * j + 0][kp] = __byte_perm(u[j], w[j], 0x5410);
                Bs[ng * 8 + 2 * j + 1][kp] = __byte_perm(u[j], w[j], 0x7632);
            }
        }
        __syncthreads();

        if (kt + 1 < NK) {
            int k0 = (kt + 1) * 32;
            const uint4* ap = (const uint4*)(A + (size_t)(brow + ar) * K + k0 + ah * 16);
            apf0 = ap[0]; apf1 = ap[1];
            const __half* b0p = B + (size_t)(k0 + 2 * kp) * N + bcol + ng * 8;
            bpf0 = *(const uint4*)b0p;
            bpf1 = *(const uint4*)(b0p + N);
        }

        const uint32_t* Asw = (const uint32_t*)As;  // row stride 20 words
#pragma unroll
        for (int ks = 0; ks < 2; ks++) {
            uint32_t ra[2][4];
#pragma unroll
            for (int mi = 0; mi < 2; mi++) {
                int r0 = wm + mi * 16 + (l >> 2);
                ra[mi][0] = Asw[(r0 + 0) * 20 + ks * 8 + (l & 3) + 0];
                ra[mi][1] = Asw[(r0 + 8) * 20 + ks * 8 + (l & 3) + 0];
                ra[mi][2] = Asw[(r0 + 0) * 20 + ks * 8 + (l & 3) + 4];
                ra[mi][3] = Asw[(r0 + 8) * 20 + ks * 8 + (l & 3) + 4];
            }
#pragma unroll
            for (int nt = 0; nt < 8; nt++) {
                int n = wn + nt * 8 + (l >> 2);
                uint32_t b0 = Bs[n][ks * 8 + (l & 3) + 0];
                uint32_t b1 = Bs[n][ks * 8 + (l & 3) + 4];
                mma16816(acc[0][nt], ra[0][0], ra[0][1], ra[0][2], ra[0][3], b0, b1);
                mma16816(acc[1][nt], ra[1][0], ra[1][1], ra[1][2], ra[1][3], b0, b1);
            }
        }
        __syncthreads();
    }

    // epilogue
#pragma unroll
    for (int nt = 0; nt < 8; nt++) {
        int col = bcol + wn + nt * 8 + (l & 3) * 2;
        float2 bv = *(const float2*)&bias[col];
#pragma unroll
        for (int mi = 0; mi < 2; mi++) {
            int r0 = brow + wm + mi * 16 + (l >> 2);
            int r1 = r0 + 8;
            float v0 = acc[mi][nt][0] + bv.x;
            float v1 = acc[mi][nt][1] + bv.y;
            float v2 = acc[mi][nt][2] + bv.x;
            float v3 = acc[mi][nt][3] + bv.y;
            if (OUT_F32) {
                float* C = (float*)Cout;
                *(float2*)&C[(size_t)r0 * N + col] = make_float2(v0, v1);
                *(float2*)&C[(size_t)r1 * N + col] = make_float2(v2, v3);
            } else {
                __half* C = (__half*)Cout;
                *(uint32_t*)&C[(size_t)r0 * N + col] = packf2h(v0, v1);
                *(uint32_t*)&C[(size_t)r1 * N + col] = packf2h(v2, v3);
            }
        }
    }
}

// --------------------- flash attention (fp16 mma, FA2) -----------------------
// Block: 64 queries (4 warps x m16), grid = (T/64, H). 64-key SMEM tiles.
__global__ __launch_bounds__(128) void flash_mma()
{
    __shared__ __half Ks[64][72];   // [key][d]
    __shared__ __half Vs[64][72];   // [d][key]  (from g_vt)

    const int h   = blockIdx.y;
    const int qb  = blockIdx.x * 64;
    const int tid = threadIdx.x;
    const int w   = tid >> 5;
    const int l   = tid & 31;

    const int r0 = qb + w * 16 + (l >> 2);
    const int r1 = r0 + 8;

    // Q fragments (pre-scaled by 1/sqrt(64) = 0.125, exact in fp16)
    uint32_t qa[4][4];
    {
        const __half2 sc = __float2half2_rn(0.125f);
#pragma unroll
        for (int ks = 0; ks < 4; ks++) {
            size_t c0 = (size_t)h * 64 + ks * 16 + (l & 3) * 2;
            __half2 v0 = *(const __half2*)&g_qkvh[(size_t)r0 * QKV_N + c0];
            __half2 v1 = *(const __half2*)&g_qkvh[(size_t)r1 * QKV_N + c0];
            __half2 v2 = *(const __half2*)&g_qkvh[(size_t)r0 * QKV_N + c0 + 8];
            __half2 v3 = *(const __half2*)&g_qkvh[(size_t)r1 * QKV_N + c0 + 8];
            v0 = __hmul2(v0, sc); v1 = __hmul2(v1, sc);
            v2 = __hmul2(v2, sc); v3 = __hmul2(v3, sc);
            qa[ks][0] = *(uint32_t*)&v0; qa[ks][1] = *(uint32_t*)&v1;
            qa[ks][2] = *(uint32_t*)&v2; qa[ks][3] = *(uint32_t*)&v3;
        }
    }

    float o[8][4];
#pragma unroll
    for (int dt = 0; dt < 8; dt++)
#pragma unroll
        for (int j = 0; j < 4; j++) o[dt][j] = 0.0f;
    float m0 = -1e30f, m1 = -1e30f, l0 = 0.0f, l1 = 0.0f;

    const int lr = tid >> 1, lh = tid & 1;   // tile loader mapping

    for (int kt = 0; kt <= qb; kt += 64) {
        // load K tile [key][d] and V^T tile [d][key]
        {
            const uint4* ks_src = (const uint4*)&g_qkvh[(size_t)(kt + lr) * QKV_N + 768 + h * 64 + lh * 32];
            const uint4* vs_src = (const uint4*)&g_vt[(size_t)(h * 64 + lr) * T_SEQ + kt + lh * 32];
#pragma unroll
            for (int j = 0; j < 4; j++) {
                *(uint4*)&Ks[lr][lh * 32 + j * 8] = ks_src[j];
                *(uint4*)&Vs[lr][lh * 32 + j * 8] = vs_src[j];
            }
        }
        __syncthreads();

        // S = Q K^T
        float s[8][4];
#pragma unroll
        for (int nt = 0; nt < 8; nt++)
#pragma unroll
            for (int j = 0; j < 4; j++) s[nt][j] = 0.0f;
#pragma unroll
        for (int ks = 0; ks < 4; ks++) {
#pragma unroll
            for (int nt = 0; nt < 8; nt++) {
                int key = nt * 8 + (l >> 2);
                uint32_t b0 = *(const uint32_t*)&Ks[key][ks * 16 + (l & 3) * 2];
                uint32_t b1 = *(const uint32_t*)&Ks[key][ks * 16 + 8 + (l & 3) * 2];
                mma16816(s[nt], qa[ks][0], qa[ks][1], qa[ks][2], qa[ks][3], b0, b1);
            }
        }

        // causal mask (only the diagonal tile needs it)
        if (kt == qb) {
#pragma unroll
            for (int nt = 0; nt < 8; nt++) {
                int col = kt + nt * 8 + (l & 3) * 2;
                if (col     > r0) s[nt][0] = -1e30f;
                if (col + 1 > r0) s[nt][1] = -1e30f;
                if (col     > r1) s[nt][2] = -1e30f;
                if (col + 1 > r1) s[nt][3] = -1e30f;
            }
        }

        // online softmax
        float mt0 = -1e30f, mt1 = -1e30f;
#pragma unroll
        for (int nt = 0; nt < 8; nt++) {
            mt0 = fmaxf(mt0, fmaxf(s[nt][0], s[nt][1]));
            mt1 = fmaxf(mt1, fmaxf(s[nt][2], s[nt][3]));
        }
        mt0 = fmaxf(mt0, __shfl_xor_sync(0xFFFFFFFF, mt0, 1));
        mt0 = fmaxf(mt0, __shfl_xor_sync(0xFFFFFFFF, mt0, 2));
        mt1 = fmaxf(mt1, __shfl_xor_sync(0xFFFFFFFF, mt1, 1));
        mt1 = fmaxf(mt1, __shfl_xor_sync(0xFFFFFFFF, mt1, 2));

        float m0n = fmaxf(m0, mt0), m1n = fmaxf(m1, mt1);
        float corr0 = __expf(m0 - m0n), corr1 = __expf(m1 - m1n);
        m0 = m0n; m1 = m1n;
        l0 *= corr0; l1 *= corr1;
#pragma unroll
        for (int dt = 0; dt < 8; dt++) {
            o[dt][0] *= corr0; o[dt][1] *= corr0;
            o[dt][2] *= corr1; o[dt][3] *= corr1;
        }

        // P = exp(S - m), convert to fp16 A-fragments
        uint32_t pa[4][4];
#pragma unroll
        for (int nt = 0; nt < 8; nt++) {
            float p0 = __expf(s[nt][0] - m0n);
            float p1 = __expf(s[nt][1] - m0n);
            float p2 = __expf(s[nt][2] - m1n);
            float p3 = __expf(s[nt][3] - m1n);
            l0 += p0 + p1;
            l1 += p2 + p3;
            int ks = nt >> 1, hi = (nt & 1) * 2;
            pa[ks][hi + 0] = packf2h(p0, p1);
            pa[ks][hi + 1] = packf2h(p2, p3);
        }

        // O += P V
#pragma unroll
        for (int ks = 0; ks < 4; ks++) {
#pragma unroll
            for (int dt = 0; dt < 8; dt++) {
                int d = dt * 8 + (l >> 2);
                uint32_t b0 = *(const uint32_t*)&Vs[d][ks * 16 + (l & 3) * 2];
                uint32_t b1 = *(const uint32_t*)&Vs[d][ks * 16 + 8 + (l & 3) * 2];
                mma16816(o[dt], pa[ks][0], pa[ks][1], pa[ks][2], pa[ks][3], b0, b1);
            }
        }
        __syncthreads();
    }

    // finalize: reduce l across the quad, normalize, store fp16
    l0 += __shfl_xor_sync(0xFFFFFFFF, l0, 1);
    l0 += __shfl_xor_sync(0xFFFFFFFF, l0, 2);
    l1 += __shfl_xor_sync(0xFFFFFFFF, l1, 1);
    l1 += __shfl_xor_sync(0xFFFFFFFF, l1, 2);
    float inv0 = 1.0f / l0, inv1 = 1.0f / l1;

#pragma unroll
    for (int dt = 0; dt < 8; dt++) {
        int d = h * 64 + dt * 8 + (l & 3) * 2;
        *(uint32_t*)&g_yh[(size_t)r0 * C_DIM + d] = packf2h(o[dt][0] * inv0, o[dt][1] * inv0);
        *(uint32_t*)&g_yh[(size_t)r1 * C_DIM + d] = packf2h(o[dt][2] * inv1, o[dt][3] * inv1);
    }
}

// ------------------------------------------------------------------------------
extern "C" void kernel_launch(void* const* d_in, const int* in_sizes, int n_in,
                              void* d_out, int out_size)
{
    const float* x      = (const float*)d_in[0];
    const float* w_attn = (const float*)d_in[1];
    const float* b_attn = (const float*)d_in[2];
    const float* w_proj = (const float*)d_in[3];
    const float* b_proj = (const float*)d_in[4];
    float* out = (float*)d_out;

    __half *xh, *wah, *wph, *qkvh, *yh;
    cudaGetSymbolAddress((void**)&xh,   g_xh);
    cudaGetSymbolAddress((void**)&wah,  g_wah);
    cudaGetSymbolAddress((void**)&wph,  g_wph);
    cudaGetSymbolAddress((void**)&qkvh, g_qkvh);
    cudaGetSymbolAddress((void**)&yh,   g_yh);

    // fp32 -> fp16 conversions
    {
        int n4 = T_SEQ * C_DIM / 4;
        cvt_f2h<<<(n4 + 255) / 256, 256>>>((const float4*)x, (uint2*)xh, n4);
        n4 = C_DIM * QKV_N / 4;
        cvt_f2h<<<(n4 + 255) / 256, 256>>>((const float4*)w_attn, (uint2*)wah, n4);
        n4 = C_DIM * C_DIM / 4;
        cvt_f2h<<<(n4 + 255) / 256, 256>>>((const float4*)w_proj, (uint2*)wph, n4);
    }

    // qkv = x @ w_attn + b_attn  (fp16 out)
    hgemm_bias<false><<<dim3(QKV_N / 128, T_SEQ / 128), 256>>>(
        xh, wah, b_attn, qkvh, T_SEQ, QKV_N, C_DIM);

    // V -> V^T
    transpose_v<<<dim3(T_SEQ / 32, C_DIM / 32), 256>>>();

    // flash attention -> y (fp16)
    flash_mma<<<dim3(T_SEQ / 64, H_NUM), 128>>>();

    // out = y @ w_proj + b_proj  (fp32 out)
    hgemm_bias<true><<<dim3(C_DIM / 128, T_SEQ / 128), 256>>>(
        yh, wph, b_proj, out, T_SEQ, C_DIM, C_DIM);
}

// round 5
// speedup vs baseline: 8.3855x; 1.2894x over previous
#include <cuda_runtime.h>
#include <cuda_fp16.h>
#include <stdint.h>

#define T_SEQ   4096
#define C_DIM   768
#define H_NUM   12
#define D_HEAD  64
#define QKV_N   2304

// ------------------------- scratch (allocation-free) -------------------------
__device__ __half g_xh  [T_SEQ * C_DIM];
__device__ __half g_wah [C_DIM * QKV_N];
__device__ __half g_wph [C_DIM * C_DIM];
__device__ __half g_qkvh[T_SEQ * QKV_N];
__device__ __half g_vt  [C_DIM * T_SEQ];   // V transposed: [channel(h*64+d)][t]
__device__ __half g_yh  [T_SEQ * C_DIM];

// ------------------------------ helpers --------------------------------------
__device__ __forceinline__ void mma16816(float* c,
    uint32_t a0, uint32_t a1, uint32_t a2, uint32_t a3,
    uint32_t b0, uint32_t b1)
{
    asm volatile(
        "mma.sync.aligned.m16n8k16.row.col.f32.f16.f16.f32 "
        "{%0,%1,%2,%3},{%4,%5,%6,%7},{%8,%9},{%0,%1,%2,%3};"
        : "+f"(c[0]), "+f"(c[1]), "+f"(c[2]), "+f"(c[3])
        : "r"(a0), "r"(a1), "r"(a2), "r"(a3), "r"(b0), "r"(b1));
}

__device__ __forceinline__ uint32_t packf2h(float lo, float hi) {
    uint32_t r;
    asm("cvt.rn.f16x2.f32 %0, %1, %2;" : "=r"(r) : "f"(hi), "f"(lo));
    return r;
}

__device__ __forceinline__ uint32_t smem_u32(const void* p) {
    return (uint32_t)__cvta_generic_to_shared(p);
}
__device__ __forceinline__ void cp16(uint32_t dst, const void* src) {
    asm volatile("cp.async.cg.shared.global [%0], [%1], 16;" :: "r"(dst), "l"(src));
}
__device__ __forceinline__ void cp_commit() {
    asm volatile("cp.async.commit_group;");
}
__device__ __forceinline__ void cp_wait1() {
    asm volatile("cp.async.wait_group 1;");
}
__device__ __forceinline__ void cp_wait0() {
    asm volatile("cp.async.wait_group 0;");
}
__device__ __forceinline__ void ldsm4(uint32_t* r, uint32_t a) {
    asm volatile("ldmatrix.sync.aligned.m8n8.x4.shared.b16 {%0,%1,%2,%3}, [%4];"
                 : "=r"(r[0]), "=r"(r[1]), "=r"(r[2]), "=r"(r[3]) : "r"(a));
}
__device__ __forceinline__ void ldsm4t(uint32_t* r, uint32_t a) {
    asm volatile("ldmatrix.sync.aligned.m8n8.x4.trans.shared.b16 {%0,%1,%2,%3}, [%4];"
                 : "=r"(r[0]), "=r"(r[1]), "=r"(r[2]), "=r"(r[3]) : "r"(a));
}

// ------------------------- fp32 -> fp16 conversion ---------------------------
__global__ void cvt_f2h(const float4* __restrict__ src, uint2* __restrict__ dst, int n4)
{
    int i = blockIdx.x * blockDim.x + threadIdx.x;
    if (i >= n4) return;
    float4 v = src[i];
    uint2 o;
    o.x = packf2h(v.x, v.y);
    o.y = packf2h(v.z, v.w);
    dst[i] = o;
}

// ------------------- V transpose: [t][1536 + c] -> [c][t] ---------------------
__global__ __launch_bounds__(256) void transpose_v()
{
    __shared__ __half tile[32][36];
    const int tb = blockIdx.x * 32;
    const int cb = blockIdx.y * 32;
    const int r  = threadIdx.x >> 3;
    const int c4 = (threadIdx.x & 7) * 4;

    *(uint2*)&tile[r][c4] =
        *(const uint2*)&g_qkvh[(size_t)(tb + r) * QKV_N + 1536 + cb + c4];
    __syncthreads();

    __half2 h0 = __halves2half2(tile[c4 + 0][r], tile[c4 + 1][r]);
    __half2 h1 = __halves2half2(tile[c4 + 2][r], tile[c4 + 3][r]);
    uint2 o = { *(uint32_t*)&h0, *(uint32_t*)&h1 };
    *(uint2*)&g_vt[(size_t)(cb + r) * T_SEQ + tb + c4] = o;
}

// ----------------------- fp16 MMA GEMM with fused bias -----------------------
// Block 128x128x32, 256 threads = 8 warps (4M x 2N), warp tile 32x64.
// cp.async double-buffered tiles; ldmatrix fragments; B tile kept k-major.
template<bool OUT_F32>
__global__ __launch_bounds__(256) void hgemm_bias(
    const __half* __restrict__ A, const __half* __restrict__ B,
    const float* __restrict__ bias, void* __restrict__ Cout,
    int M, int N, int K)
{
    __shared__ __half As[2][128][40];   // [m][k], pad 8
    __shared__ __half Bs[2][32][136];   // [k][n], pad 8

    const int tid = threadIdx.x;
    const int l   = tid & 31;
    const int wid = tid >> 5;
    const int wm  = (wid & 3) * 32;
    const int wn  = (wid >> 2) * 64;
    const int brow = blockIdx.y * 128;
    const int bcol = blockIdx.x * 128;

    // A: 128 rows x 32 halves; 2 threads/row, 16 halves (2 chunks) each.
    const int ar = tid >> 1, ac = (tid & 1) * 16;
    // B: 32 rows x 128 halves; 8 threads/row, 16 halves (2 chunks) each.
    const int bkr = tid >> 3, bc = (tid & 7) * 16;

    float acc[2][8][4];
#pragma unroll
    for (int mi = 0; mi < 2; mi++)
#pragma unroll
        for (int nt = 0; nt < 8; nt++)
#pragma unroll
            for (int j = 0; j < 4; j++) acc[mi][nt][j] = 0.0f;

    const int NK = K / 32;

    // prologue: stage k-tile 0
    {
        const __half* asrc = A + (size_t)(brow + ar) * K + ac;
        const __half* bsrc = B + (size_t)bkr * N + bcol + bc;
        cp16(smem_u32(&As[0][ar][ac]),     asrc);
        cp16(smem_u32(&As[0][ar][ac + 8]), asrc + 8);
        cp16(smem_u32(&Bs[0][bkr][bc]),     bsrc);
        cp16(smem_u32(&Bs[0][bkr][bc + 8]), bsrc + 8);
        cp_commit();
    }

    for (int kt = 0; kt < NK; kt++) {
        const int buf = kt & 1;
        if (kt + 1 < NK) {
            const int k0 = (kt + 1) * 32;
            const __half* asrc = A + (size_t)(brow + ar) * K + k0 + ac;
            const __half* bsrc = B + (size_t)(k0 + bkr) * N + bcol + bc;
            cp16(smem_u32(&As[buf ^ 1][ar][ac]),     asrc);
            cp16(smem_u32(&As[buf ^ 1][ar][ac + 8]), asrc + 8);
            cp16(smem_u32(&Bs[buf ^ 1][bkr][bc]),     bsrc);
            cp16(smem_u32(&Bs[buf ^ 1][bkr][bc + 8]), bsrc + 8);
            cp_commit();
            cp_wait1();
        } else {
            cp_wait0();
        }
        __syncthreads();

#pragma unroll
        for (int ks = 0; ks < 2; ks++) {
            uint32_t ra[2][4];
#pragma unroll
            for (int mi = 0; mi < 2; mi++)
                ldsm4(ra[mi], smem_u32(&As[buf][wm + mi * 16 + (l & 15)][ks * 16 + (l >> 4) * 8]));
#pragma unroll
            for (int ntp = 0; ntp < 4; ntp++) {
                uint32_t rb[4];
                ldsm4t(rb, smem_u32(&Bs[buf][ks * 16 + (l & 15)][wn + ntp * 16 + (l >> 4) * 8]));
                mma16816(acc[0][2 * ntp],     ra[0][0], ra[0][1], ra[0][2], ra[0][3], rb[0], rb[1]);
                mma16816(acc[1][2 * ntp],     ra[1][0], ra[1][1], ra[1][2], ra[1][3], rb[0], rb[1]);
                mma16816(acc[0][2 * ntp + 1], ra[0][0], ra[0][1], ra[0][2], ra[0][3], rb[2], rb[3]);
                mma16816(acc[1][2 * ntp + 1], ra[1][0], ra[1][1], ra[1][2], ra[1][3], rb[2], rb[3]);
            }
        }
        __syncthreads();
    }

    // epilogue
#pragma unroll
    for (int nt = 0; nt < 8; nt++) {
        int col = bcol + wn + nt * 8 + (l & 3) * 2;
        float2 bv = *(const float2*)&bias[col];
#pragma unroll
        for (int mi = 0; mi < 2; mi++) {
            int r0 = brow + wm + mi * 16 + (l >> 2);
            int r1 = r0 + 8;
            float v0 = acc[mi][nt][0] + bv.x;
            float v1 = acc[mi][nt][1] + bv.y;
            float v2 = acc[mi][nt][2] + bv.x;
            float v3 = acc[mi][nt][3] + bv.y;
            if (OUT_F32) {
                float* C = (float*)Cout;
                *(float2*)&C[(size_t)r0 * N + col] = make_float2(v0, v1);
                *(float2*)&C[(size_t)r1 * N + col] = make_float2(v2, v3);
            } else {
                __half* C = (__half*)Cout;
                *(uint32_t*)&C[(size_t)r0 * N + col] = packf2h(v0, v1);
                *(uint32_t*)&C[(size_t)r1 * N + col] = packf2h(v2, v3);
            }
        }
    }
}

// --------------------- flash attention (fp16 mma, FA2) -----------------------
// Block: 64 queries (4 warps x m16), grid = (T/64, H). 64-key tiles,
// cp.async double-buffered, ldmatrix fragments.
__global__ __launch_bounds__(128) void flash_mma()
{
    __shared__ __half Ks[2][64][72];   // [key][d]
    __shared__ __half Vs[2][64][72];   // [d][key]

    const int h   = blockIdx.y;
    const int qb  = blockIdx.x * 64;
    const int tid = threadIdx.x;
    const int w   = tid >> 5;
    const int l   = tid & 31;

    const int r0 = qb + w * 16 + (l >> 2);
    const int r1 = r0 + 8;

    // Q fragments (pre-scaled by 1/sqrt(64) = 0.125, exact in fp16)
    uint32_t qa[4][4];
    {
        const __half2 sc = __float2half2_rn(0.125f);
#pragma unroll
        for (int ks = 0; ks < 4; ks++) {
            size_t c0 = (size_t)h * 64 + ks * 16 + (l & 3) * 2;
            __half2 v0 = *(const __half2*)&g_qkvh[(size_t)r0 * QKV_N + c0];
            __half2 v1 = *(const __half2*)&g_qkvh[(size_t)r1 * QKV_N + c0];
            __half2 v2 = *(const __half2*)&g_qkvh[(size_t)r0 * QKV_N + c0 + 8];
            __half2 v3 = *(const __half2*)&g_qkvh[(size_t)r1 * QKV_N + c0 + 8];
            v0 = __hmul2(v0, sc); v1 = __hmul2(v1, sc);
            v2 = __hmul2(v2, sc); v3 = __hmul2(v3, sc);
            qa[ks][0] = *(uint32_t*)&v0; qa[ks][1] = *(uint32_t*)&v1;
            qa[ks][2] = *(uint32_t*)&v2; qa[ks][3] = *(uint32_t*)&v3;
        }
    }

    float o[8][4];
#pragma unroll
    for (int dt = 0; dt < 8; dt++)
#pragma unroll
        for (int j = 0; j < 4; j++) o[dt][j] = 0.0f;
    float m0 = -1e30f, m1 = -1e30f, l0 = 0.0f, l1 = 0.0f;

    const int lr = tid >> 1;          // 0..63
    const int lc = (tid & 1) * 32;    // 0 or 32 (halves)

    // prologue: stage tile 0
    {
        const __half* ksrc = &g_qkvh[(size_t)lr * QKV_N + 768 + h * 64 + lc];
        const __half* vsrc = &g_vt[(size_t)(h * 64 + lr) * T_SEQ + lc];
#pragma unroll
        for (int j = 0; j < 4; j++) {
            cp16(smem_u32(&Ks[0][lr][lc + j * 8]), ksrc + j * 8);
            cp16(smem_u32(&Vs[0][lr][lc + j * 8]), vsrc + j * 8);
        }
        cp_commit();
    }

    const int ntiles = qb / 64 + 1;
    for (int it = 0; it < ntiles; it++) {
        const int kt  = it * 64;
        const int buf = it & 1;
        if (it + 1 < ntiles) {
            const int kn = kt + 64;
            const __half* ksrc = &g_qkvh[(size_t)(kn + lr) * QKV_N + 768 + h * 64 + lc];
            const __half* vsrc = &g_vt[(size_t)(h * 64 + lr) * T_SEQ + kn + lc];
#pragma unroll
            for (int j = 0; j < 4; j++) {
                cp16(smem_u32(&Ks[buf ^ 1][lr][lc + j * 8]), ksrc + j * 8);
                cp16(smem_u32(&Vs[buf ^ 1][lr][lc + j * 8]), vsrc + j * 8);
            }
            cp_commit();
            cp_wait1();
        } else {
            cp_wait0();
        }
        __syncthreads();

        // S = Q K^T   (Ks is [n][k] -> non-trans ldmatrix gives B fragments)
        float s[8][4];
#pragma unroll
        for (int nt = 0; nt < 8; nt++)
#pragma unroll
            for (int j = 0; j < 4; j++) s[nt][j] = 0.0f;
#pragma unroll
        for (int ks = 0; ks < 4; ks++) {
#pragma unroll
            for (int ntp = 0; ntp < 4; ntp++) {
                uint32_t rb[4];
                ldsm4(rb, smem_u32(&Ks[buf][ntp * 16 + (l & 7) + ((l & 16) >> 1)][ks * 16 + (l & 8)]));
                mma16816(s[2 * ntp],     qa[ks][0], qa[ks][1], qa[ks][2], qa[ks][3], rb[0], rb[1]);
                mma16816(s[2 * ntp + 1], qa[ks][0], qa[ks][1], qa[ks][2], qa[ks][3], rb[2], rb[3]);
            }
        }

        // causal mask (diagonal tile only)
        if (kt == qb) {
#pragma unroll
            for (int nt = 0; nt < 8; nt++) {
                int col = kt + nt * 8 + (l & 3) * 2;
                if (col     > r0) s[nt][0] = -1e30f;
                if (col + 1 > r0) s[nt][1] = -1e30f;
                if (col     > r1) s[nt][2] = -1e30f;
                if (col + 1 > r1) s[nt][3] = -1e30f;
            }
        }

        // online softmax
        float mt0 = -1e30f, mt1 = -1e30f;
#pragma unroll
        for (int nt = 0; nt < 8; nt++) {
            mt0 = fmaxf(mt0, fmaxf(s[nt][0], s[nt][1]));
            mt1 = fmaxf(mt1, fmaxf(s[nt][2], s[nt][3]));
        }
        mt0 = fmaxf(mt0, __shfl_xor_sync(0xFFFFFFFF, mt0, 1));
        mt0 = fmaxf(mt0, __shfl_xor_sync(0xFFFFFFFF, mt0, 2));
        mt1 = fmaxf(mt1, __shfl_xor_sync(0xFFFFFFFF, mt1, 1));
        mt1 = fmaxf(mt1, __shfl_xor_sync(0xFFFFFFFF, mt1, 2));

        float m0n = fmaxf(m0, mt0), m1n = fmaxf(m1, mt1);
        float corr0 = __expf(m0 - m0n), corr1 = __expf(m1 - m1n);
        m0 = m0n; m1 = m1n;
        l0 *= corr0; l1 *= corr1;
#pragma unroll
        for (int dt = 0; dt < 8; dt++) {
            o[dt][0] *= corr0; o[dt][1] *= corr0;
            o[dt][2] *= corr1; o[dt][3] *= corr1;
        }

        // P = exp(S - m) -> fp16 A-fragments
        uint32_t pa[4][4];
#pragma unroll
        for (int nt = 0; nt < 8; nt++) {
            float p0 = __expf(s[nt][0] - m0n);
            float p1 = __expf(s[nt][1] - m0n);
            float p2 = __expf(s[nt][2] - m1n);
            float p3 = __expf(s[nt][3] - m1n);
            l0 += p0 + p1;
            l1 += p2 + p3;
            int ks = nt >> 1, hi = (nt & 1) * 2;
            pa[ks][hi + 0] = packf2h(p0, p1);
            pa[ks][hi + 1] = packf2h(p2, p3);
        }

        // O += P V   (Vs is [d][key] = [n][k] -> non-trans ldmatrix)
#pragma unroll
        for (int ks = 0; ks < 4; ks++) {
#pragma unroll
            for (int dtp = 0; dtp < 4; dtp++) {
                uint32_t rb[4];
                ldsm4(rb, smem_u32(&Vs[buf][dtp * 16 + (l & 7) + ((l & 16) >> 1)][ks * 16 + (l & 8)]));
                mma16816(o[2 * dtp],     pa[ks][0], pa[ks][1], pa[ks][2], pa[ks][3], rb[0], rb[1]);
                mma16816(o[2 * dtp + 1], pa[ks][0], pa[ks][1], pa[ks][2], pa[ks][3], rb[2], rb[3]);
            }
        }
        __syncthreads();
    }

    // finalize
    l0 += __shfl_xor_sync(0xFFFFFFFF, l0, 1);
    l0 += __shfl_xor_sync(0xFFFFFFFF, l0, 2);
    l1 += __shfl_xor_sync(0xFFFFFFFF, l1, 1);
    l1 += __shfl_xor_sync(0xFFFFFFFF, l1, 2);
    float inv0 = 1.0f / l0, inv1 = 1.0f / l1;

#pragma unroll
    for (int dt = 0; dt < 8; dt++) {
        int d = h * 64 + dt * 8 + (l & 3) * 2;
        *(uint32_t*)&g_yh[(size_t)r0 * C_DIM + d] = packf2h(o[dt][0] * inv0, o[dt][1] * inv0);
        *(uint32_t*)&g_yh[(size_t)r1 * C_DIM + d] = packf2h(o[dt][2] * inv1, o[dt][3] * inv1);
    }
}

// ------------------------------------------------------------------------------
extern "C" void kernel_launch(void* const* d_in, const int* in_sizes, int n_in,
                              void* d_out, int out_size)
{
    const float* x      = (const float*)d_in[0];
    const float* w_attn = (const float*)d_in[1];
    const float* b_attn = (const float*)d_in[2];
    const float* w_proj = (const float*)d_in[3];
    const float* b_proj = (const float*)d_in[4];
    float* out = (float*)d_out;

    __half *xh, *wah, *wph, *qkvh, *yh;
    cudaGetSymbolAddress((void**)&xh,   g_xh);
    cudaGetSymbolAddress((void**)&wah,  g_wah);
    cudaGetSymbolAddress((void**)&wph,  g_wph);
    cudaGetSymbolAddress((void**)&qkvh, g_qkvh);
    cudaGetSymbolAddress((void**)&yh,   g_yh);

    {
        int n4 = T_SEQ * C_DIM / 4;
        cvt_f2h<<<(n4 + 255) / 256, 256>>>((const float4*)x, (uint2*)xh, n4);
        n4 = C_DIM * QKV_N / 4;
        cvt_f2h<<<(n4 + 255) / 256, 256>>>((const float4*)w_attn, (uint2*)wah, n4);
        n4 = C_DIM * C_DIM / 4;
        cvt_f2h<<<(n4 + 255) / 256, 256>>>((const float4*)w_proj, (uint2*)wph, n4);
    }

    hgemm_bias<false><<<dim3(QKV_N / 128, T_SEQ / 128), 256>>>(
        xh, wah, b_attn, qkvh, T_SEQ, QKV_N, C_DIM);

    transpose_v<<<dim3(T_SEQ / 32, C_DIM / 32), 256>>>();

    flash_mma<<<dim3(T_SEQ / 64, H_NUM), 128>>>();

    hgemm_bias<true><<<dim3(C_DIM / 128, T_SEQ / 128), 256>>>(
        yh, wph, b_proj, out, T_SEQ, C_DIM, C_DIM);
}

// round 6
// speedup vs baseline: 9.0510x; 1.0794x over previous
#include <cuda_runtime.h>
#include <cuda_fp16.h>
#include <stdint.h>

#define T_SEQ   4096
#define C_DIM   768
#define H_NUM   12
#define D_HEAD  64
#define QKV_N   2304

// ------------------------- scratch (allocation-free) -------------------------
__device__ __half g_xh  [T_SEQ * C_DIM];
__device__ __half g_wah [C_DIM * QKV_N];
__device__ __half g_wph [C_DIM * C_DIM];
__device__ __half g_qkvh[T_SEQ * QKV_N];
__device__ __half g_vt  [C_DIM * T_SEQ];   // V transposed: [channel(h*64+d)][t]
__device__ __half g_yh  [T_SEQ * C_DIM];

// ------------------------------ helpers --------------------------------------
__device__ __forceinline__ void mma16816(float* c,
    uint32_t a0, uint32_t a1, uint32_t a2, uint32_t a3,
    uint32_t b0, uint32_t b1)
{
    asm volatile(
        "mma.sync.aligned.m16n8k16.row.col.f32.f16.f16.f32 "
        "{%0,%1,%2,%3},{%4,%5,%6,%7},{%8,%9},{%0,%1,%2,%3};"
        : "+f"(c[0]), "+f"(c[1]), "+f"(c[2]), "+f"(c[3])
        : "r"(a0), "r"(a1), "r"(a2), "r"(a3), "r"(b0), "r"(b1));
}

__device__ __forceinline__ uint32_t packf2h(float lo, float hi) {
    uint32_t r;
    asm("cvt.rn.f16x2.f32 %0, %1, %2;" : "=r"(r) : "f"(hi), "f"(lo));
    return r;
}

__device__ __forceinline__ uint32_t smem_u32(const void* p) {
    return (uint32_t)__cvta_generic_to_shared(p);
}
__device__ __forceinline__ void cp16(uint32_t dst, const void* src) {
    asm volatile("cp.async.cg.shared.global [%0], [%1], 16;" :: "r"(dst), "l"(src));
}
__device__ __forceinline__ void cp_commit() {
    asm volatile("cp.async.commit_group;");
}
__device__ __forceinline__ void cp_wait1() {
    asm volatile("cp.async.wait_group 1;");
}
__device__ __forceinline__ void cp_wait0() {
    asm volatile("cp.async.wait_group 0;");
}
__device__ __forceinline__ void ldsm4(uint32_t* r, uint32_t a) {
    asm volatile("ldmatrix.sync.aligned.m8n8.x4.shared.b16 {%0,%1,%2,%3}, [%4];"
                 : "=r"(r[0]), "=r"(r[1]), "=r"(r[2]), "=r"(r[3]) : "r"(a));
}
__device__ __forceinline__ void ldsm4t(uint32_t* r, uint32_t a) {
    asm volatile("ldmatrix.sync.aligned.m8n8.x4.trans.shared.b16 {%0,%1,%2,%3}, [%4];"
                 : "=r"(r[0]), "=r"(r[1]), "=r"(r[2]), "=r"(r[3]) : "r"(a));
}

// ------------------------- fp32 -> fp16 conversion ---------------------------
__global__ void cvt_f2h(const float4* __restrict__ src, uint2* __restrict__ dst, int n4)
{
    int i = blockIdx.x * blockDim.x + threadIdx.x;
    if (i >= n4) return;
    float4 v = src[i];
    uint2 o;
    o.x = packf2h(v.x, v.y);
    o.y = packf2h(v.z, v.w);
    dst[i] = o;
}

// ------------------- V transpose: [t][1536 + c] -> [c][t] ---------------------
__global__ __launch_bounds__(256) void transpose_v()
{
    __shared__ __half tile[32][36];
    const int tb = blockIdx.x * 32;
    const int cb = blockIdx.y * 32;
    const int r  = threadIdx.x >> 3;
    const int c4 = (threadIdx.x & 7) * 4;

    *(uint2*)&tile[r][c4] =
        *(const uint2*)&g_qkvh[(size_t)(tb + r) * QKV_N + 1536 + cb + c4];
    __syncthreads();

    __half2 h0 = __halves2half2(tile[c4 + 0][r], tile[c4 + 1][r]);
    __half2 h1 = __halves2half2(tile[c4 + 2][r], tile[c4 + 3][r]);
    uint2 o = { *(uint32_t*)&h0, *(uint32_t*)&h1 };
    *(uint2*)&g_vt[(size_t)(cb + r) * T_SEQ + tb + c4] = o;
}

// ----------------------- fp16 MMA GEMM with fused bias -----------------------
// Block 128x128x32, 256 threads = 8 warps (4M x 2N), warp tile 32x64.
// cp.async double-buffered tiles; ldmatrix fragments; B tile kept k-major.
template<bool OUT_F32>
__global__ __launch_bounds__(256) void hgemm_bias(
    const __half* __restrict__ A, const __half* __restrict__ B,
    const float* __restrict__ bias, void* __restrict__ Cout,
    int M, int N, int K)
{
    __shared__ __half As[2][128][40];   // [m][k], pad 8
    __shared__ __half Bs[2][32][136];   // [k][n], pad 8

    const int tid = threadIdx.x;
    const int l   = tid & 31;
    const int wid = tid >> 5;
    const int wm  = (wid & 3) * 32;
    const int wn  = (wid >> 2) * 64;
    const int brow = blockIdx.y * 128;
    const int bcol = blockIdx.x * 128;

    const int ar = tid >> 1, ac = (tid & 1) * 16;
    const int bkr = tid >> 3, bc = (tid & 7) * 16;

    float acc[2][8][4];
#pragma unroll
    for (int mi = 0; mi < 2; mi++)
#pragma unroll
        for (int nt = 0; nt < 8; nt++)
#pragma unroll
            for (int j = 0; j < 4; j++) acc[mi][nt][j] = 0.0f;

    const int NK = K / 32;

    {
        const __half* asrc = A + (size_t)(brow + ar) * K + ac;
        const __half* bsrc = B + (size_t)bkr * N + bcol + bc;
        cp16(smem_u32(&As[0][ar][ac]),     asrc);
        cp16(smem_u32(&As[0][ar][ac + 8]), asrc + 8);
        cp16(smem_u32(&Bs[0][bkr][bc]),     bsrc);
        cp16(smem_u32(&Bs[0][bkr][bc + 8]), bsrc + 8);
        cp_commit();
    }

    for (int kt = 0; kt < NK; kt++) {
        const int buf = kt & 1;
        if (kt + 1 < NK) {
            const int k0 = (kt + 1) * 32;
            const __half* asrc = A + (size_t)(brow + ar) * K + k0 + ac;
            const __half* bsrc = B + (size_t)(k0 + bkr) * N + bcol + bc;
            cp16(smem_u32(&As[buf ^ 1][ar][ac]),     asrc);
            cp16(smem_u32(&As[buf ^ 1][ar][ac + 8]), asrc + 8);
            cp16(smem_u32(&Bs[buf ^ 1][bkr][bc]),     bsrc);
            cp16(smem_u32(&Bs[buf ^ 1][bkr][bc + 8]), bsrc + 8);
            cp_commit();
            cp_wait1();
        } else {
            cp_wait0();
        }
        __syncthreads();

#pragma unroll
        for (int ks = 0; ks < 2; ks++) {
            uint32_t ra[2][4];
#pragma unroll
            for (int mi = 0; mi < 2; mi++)
                ldsm4(ra[mi], smem_u32(&As[buf][wm + mi * 16 + (l & 15)][ks * 16 + (l >> 4) * 8]));
#pragma unroll
            for (int ntp = 0; ntp < 4; ntp++) {
                uint32_t rb[4];
                ldsm4t(rb, smem_u32(&Bs[buf][ks * 16 + (l & 15)][wn + ntp * 16 + (l >> 4) * 8]));
                mma16816(acc[0][2 * ntp],     ra[0][0], ra[0][1], ra[0][2], ra[0][3], rb[0], rb[1]);
                mma16816(acc[1][2 * ntp],     ra[1][0], ra[1][1], ra[1][2], ra[1][3], rb[0], rb[1]);
                mma16816(acc[0][2 * ntp + 1], ra[0][0], ra[0][1], ra[0][2], ra[0][3], rb[2], rb[3]);
                mma16816(acc[1][2 * ntp + 1], ra[1][0], ra[1][1], ra[1][2], ra[1][3], rb[2], rb[3]);
            }
        }
        __syncthreads();
    }

#pragma unroll
    for (int nt = 0; nt < 8; nt++) {
        int col = bcol + wn + nt * 8 + (l & 3) * 2;
        float2 bv = *(const float2*)&bias[col];
#pragma unroll
        for (int mi = 0; mi < 2; mi++) {
            int r0 = brow + wm + mi * 16 + (l >> 2);
            int r1 = r0 + 8;
            float v0 = acc[mi][nt][0] + bv.x;
            float v1 = acc[mi][nt][1] + bv.y;
            float v2 = acc[mi][nt][2] + bv.x;
            float v3 = acc[mi][nt][3] + bv.y;
            if (OUT_F32) {
                float* C = (float*)Cout;
                *(float2*)&C[(size_t)r0 * N + col] = make_float2(v0, v1);
                *(float2*)&C[(size_t)r1 * N + col] = make_float2(v2, v3);
            } else {
                __half* C = (__half*)Cout;
                *(uint32_t*)&C[(size_t)r0 * N + col] = packf2h(v0, v1);
                *(uint32_t*)&C[(size_t)r1 * N + col] = packf2h(v2, v3);
            }
        }
    }
}

// --------------------- flash attention (fp16 mma, FA2) -----------------------
// 128 queries per block (8 warps x m16), 64-key double-buffered tiles.
// Paired-chunk schedule: block bx handles chunk bx and chunk 31-bx, so every
// block does exactly 66 tiles. grid = (16, H), 256 threads.
__global__ __launch_bounds__(256) void flash_mma()
{
    __shared__ __half Ks[2][64][72];   // [key][d]
    __shared__ __half Vs[2][64][72];   // [d][key]

    const int h    = blockIdx.y;
    const int pair = blockIdx.x;       // 0..15
    const int tid  = threadIdx.x;
    const int w    = tid >> 5;
    const int l    = tid & 31;

    const int lr = tid >> 2;           // 0..63  (tile loader row)
    const int lc = (tid & 3) * 16;     // 0/16/32/48 (halves)

#pragma unroll 1
    for (int half = 0; half < 2; half++) {
        const int chunk = half ? (31 - pair) : pair;
        const int qb = chunk * 128;
        const int r0 = qb + w * 16 + (l >> 2);
        const int r1 = r0 + 8;

        // Q fragments (pre-scaled by 1/sqrt(64) = 0.125, exact in fp16)
        uint32_t qa[4][4];
        {
            const __half2 sc = __float2half2_rn(0.125f);
#pragma unroll
            for (int ks = 0; ks < 4; ks++) {
                size_t c0 = (size_t)h * 64 + ks * 16 + (l & 3) * 2;
                __half2 v0 = *(const __half2*)&g_qkvh[(size_t)r0 * QKV_N + c0];
                __half2 v1 = *(const __half2*)&g_qkvh[(size_t)r1 * QKV_N + c0];
                __half2 v2 = *(const __half2*)&g_qkvh[(size_t)r0 * QKV_N + c0 + 8];
                __half2 v3 = *(const __half2*)&g_qkvh[(size_t)r1 * QKV_N + c0 + 8];
                v0 = __hmul2(v0, sc); v1 = __hmul2(v1, sc);
                v2 = __hmul2(v2, sc); v3 = __hmul2(v3, sc);
                qa[ks][0] = *(uint32_t*)&v0; qa[ks][1] = *(uint32_t*)&v1;
                qa[ks][2] = *(uint32_t*)&v2; qa[ks][3] = *(uint32_t*)&v3;
            }
        }

        float o[8][4];
#pragma unroll
        for (int dt = 0; dt < 8; dt++)
#pragma unroll
            for (int j = 0; j < 4; j++) o[dt][j] = 0.0f;
        float m0 = -1e30f, m1 = -1e30f, l0 = 0.0f, l1 = 0.0f;

        // prologue: stage tile 0
        {
            const __half* ksrc = &g_qkvh[(size_t)lr * QKV_N + 768 + h * 64 + lc];
            const __half* vsrc = &g_vt[(size_t)(h * 64 + lr) * T_SEQ + lc];
            cp16(smem_u32(&Ks[0][lr][lc]),     ksrc);
            cp16(smem_u32(&Ks[0][lr][lc + 8]), ksrc + 8);
            cp16(smem_u32(&Vs[0][lr][lc]),     vsrc);
            cp16(smem_u32(&Vs[0][lr][lc + 8]), vsrc + 8);
            cp_commit();
        }

        const int ntiles = qb / 64 + 2;   // keys 0 .. qb+127
        for (int it = 0; it < ntiles; it++) {
            const int kt  = it * 64;
            const int buf = it & 1;
            if (it + 1 < ntiles) {
                const int kn = kt + 64;
                const __half* ksrc = &g_qkvh[(size_t)(kn + lr) * QKV_N + 768 + h * 64 + lc];
                const __half* vsrc = &g_vt[(size_t)(h * 64 + lr) * T_SEQ + kn + lc];
                cp16(smem_u32(&Ks[buf ^ 1][lr][lc]),     ksrc);
                cp16(smem_u32(&Ks[buf ^ 1][lr][lc + 8]), ksrc + 8);
                cp16(smem_u32(&Vs[buf ^ 1][lr][lc]),     vsrc);
                cp16(smem_u32(&Vs[buf ^ 1][lr][lc + 8]), vsrc + 8);
                cp_commit();
                cp_wait1();
            } else {
                cp_wait0();
            }
            __syncthreads();

            // S = Q K^T   (Ks is [n][k] -> non-trans ldmatrix gives B fragments)
            float s[8][4];
#pragma unroll
            for (int nt = 0; nt < 8; nt++)
#pragma unroll
                for (int j = 0; j < 4; j++) s[nt][j] = 0.0f;
#pragma unroll
            for (int ks = 0; ks < 4; ks++) {
#pragma unroll
                for (int ntp = 0; ntp < 4; ntp++) {
                    uint32_t rb[4];
                    ldsm4(rb, smem_u32(&Ks[buf][ntp * 16 + (l & 7) + ((l & 16) >> 1)][ks * 16 + (l & 8)]));
                    mma16816(s[2 * ntp],     qa[ks][0], qa[ks][1], qa[ks][2], qa[ks][3], rb[0], rb[1]);
                    mma16816(s[2 * ntp + 1], qa[ks][0], qa[ks][1], qa[ks][2], qa[ks][3], rb[2], rb[3]);
                }
            }

            // causal mask (needed only on the last two tiles of each chunk)
            if (kt + 64 > qb) {
#pragma unroll
                for (int nt = 0; nt < 8; nt++) {
                    int col = kt + nt * 8 + (l & 3) * 2;
                    if (col     > r0) s[nt][0] = -1e30f;
                    if (col + 1 > r0) s[nt][1] = -1e30f;
                    if (col     > r1) s[nt][2] = -1e30f;
                    if (col + 1 > r1) s[nt][3] = -1e30f;
                }
            }

            // online softmax
            float mt0 = -1e30f, mt1 = -1e30f;
#pragma unroll
            for (int nt = 0; nt < 8; nt++) {
                mt0 = fmaxf(mt0, fmaxf(s[nt][0], s[nt][1]));
                mt1 = fmaxf(mt1, fmaxf(s[nt][2], s[nt][3]));
            }
            mt0 = fmaxf(mt0, __shfl_xor_sync(0xFFFFFFFF, mt0, 1));
            mt0 = fmaxf(mt0, __shfl_xor_sync(0xFFFFFFFF, mt0, 2));
            mt1 = fmaxf(mt1, __shfl_xor_sync(0xFFFFFFFF, mt1, 1));
            mt1 = fmaxf(mt1, __shfl_xor_sync(0xFFFFFFFF, mt1, 2));

            float m0n = fmaxf(m0, mt0), m1n = fmaxf(m1, mt1);
            float corr0 = __expf(m0 - m0n), corr1 = __expf(m1 - m1n);
            m0 = m0n; m1 = m1n;
            l0 *= corr0; l1 *= corr1;
#pragma unroll
            for (int dt = 0; dt < 8; dt++) {
                o[dt][0] *= corr0; o[dt][1] *= corr0;
                o[dt][2] *= corr1; o[dt][3] *= corr1;
            }

            // P = exp(S - m) -> fp16 A-fragments
            uint32_t pa[4][4];
#pragma unroll
            for (int nt = 0; nt < 8; nt++) {
                float p0 = __expf(s[nt][0] - m0n);
                float p1 = __expf(s[nt][1] - m0n);
                float p2 = __expf(s[nt][2] - m1n);
                float p3 = __expf(s[nt][3] - m1n);
                l0 += p0 + p1;
                l1 += p2 + p3;
                int ks = nt >> 1, hi = (nt & 1) * 2;
                pa[ks][hi + 0] = packf2h(p0, p1);
                pa[ks][hi + 1] = packf2h(p2, p3);
            }

            // O += P V   (Vs is [d][key] = [n][k] -> non-trans ldmatrix)
#pragma unroll
            for (int ks = 0; ks < 4; ks++) {
#pragma unroll
                for (int dtp = 0; dtp < 4; dtp++) {
                    uint32_t rb[4];
                    ldsm4(rb, smem_u32(&Vs[buf][dtp * 16 + (l & 7) + ((l & 16) >> 1)][ks * 16 + (l & 8)]));
                    mma16816(o[2 * dtp],     pa[ks][0], pa[ks][1], pa[ks][2], pa[ks][3], rb[0], rb[1]);
                    mma16816(o[2 * dtp + 1], pa[ks][0], pa[ks][1], pa[ks][2], pa[ks][3], rb[2], rb[3]);
                }
            }
            __syncthreads();
        }

        // finalize
        l0 += __shfl_xor_sync(0xFFFFFFFF, l0, 1);
        l0 += __shfl_xor_sync(0xFFFFFFFF, l0, 2);
        l1 += __shfl_xor_sync(0xFFFFFFFF, l1, 1);
        l1 += __shfl_xor_sync(0xFFFFFFFF, l1, 2);
        float inv0 = 1.0f / l0, inv1 = 1.0f / l1;

#pragma unroll
        for (int dt = 0; dt < 8; dt++) {
            int d = h * 64 + dt * 8 + (l & 3) * 2;
            *(uint32_t*)&g_yh[(size_t)r0 * C_DIM + d] = packf2h(o[dt][0] * inv0, o[dt][1] * inv0);
            *(uint32_t*)&g_yh[(size_t)r1 * C_DIM + d] = packf2h(o[dt][2] * inv1, o[dt][3] * inv1);
        }
    }
}

// ------------------------------------------------------------------------------
extern "C" void kernel_launch(void* const* d_in, const int* in_sizes, int n_in,
                              void* d_out, int out_size)
{
    const float* x      = (const float*)d_in[0];
    const float* w_attn = (const float*)d_in[1];
    const float* b_attn = (const float*)d_in[2];
    const float* w_proj = (const float*)d_in[3];
    const float* b_proj = (const float*)d_in[4];
    float* out = (float*)d_out;

    __half *xh, *wah, *wph, *qkvh, *yh;
    cudaGetSymbolAddress((void**)&xh,   g_xh);
    cudaGetSymbolAddress((void**)&wah,  g_wah);
    cudaGetSymbolAddress((void**)&wph,  g_wph);
    cudaGetSymbolAddress((void**)&qkvh, g_qkvh);
    cudaGetSymbolAddress((void**)&yh,   g_yh);

    {
        int n4 = T_SEQ * C_DIM / 4;
        cvt_f2h<<<(n4 + 255) / 256, 256>>>((const float4*)x, (uint2*)xh, n4);
        n4 = C_DIM * QKV_N / 4;
        cvt_f2h<<<(n4 + 255) / 256, 256>>>((const float4*)w_attn, (uint2*)wah, n4);
        n4 = C_DIM * C_DIM / 4;
        cvt_f2h<<<(n4 + 255) / 256, 256>>>((const float4*)w_proj, (uint2*)wph, n4);
    }

    hgemm_bias<false><<<dim3(QKV_N / 128, T_SEQ / 128), 256>>>(
        xh, wah, b_attn, qkvh, T_SEQ, QKV_N, C_DIM);

    transpose_v<<<dim3(T_SEQ / 32, C_DIM / 32), 256>>>();

    flash_mma<<<dim3(16, H_NUM), 256>>>();

    hgemm_bias<true><<<dim3(C_DIM / 128, T_SEQ / 128), 256>>>(
        yh, wph, b_proj, out, T_SEQ, C_DIM, C_DIM);
}